// round 12
// baseline (speedup 1.0000x reference)
#include <cuda_runtime.h>
#include <cuda_fp16.h>

// ---------------------------------------------------------------------------
// TPoseHuman fused 6-part MLP — layers 2 AND 3 on mma.sync fp16.
// R12: B operands bypass shared memory entirely. Prep kernels store W2/W3 in
// the exact per-lane mma.m16n8k16 B-fragment layout; the main kernel fetches
// fragments with coalesced __ldg uint4 loads (L2-resident, L1-cached).
// No cp.async ring, no B LDSM, 4 CTA barriers per part (was 10).
//   layer2: single-chain fp16 (validated rel_err ~1.6e-4 in R11)
//   layer3: 3-chain hi/lo fp16
// ---------------------------------------------------------------------------

#define NPTS    65536
#define PPARTS  6
#define TM      64
#define NCTAS   (NPTS / TM)       // 1024
#define THREADS 256
#define OUTC    27

// ---- smem byte offsets (A/h2 planes only) ----
#define OFF_AHI  0u               // 64 rows x 512B (A hi / h2 hi)
#define OFF_ALO  32768u           // 64 rows x 512B (h2 lo, layer3 only)
#define SMEM_BYTES 65536

// ---------------------------------------------------------------------------
// asm helpers (baseline PTX, sm_80-era: family-safe on compute_103)
// ---------------------------------------------------------------------------
__device__ __forceinline__ unsigned smem_to_u32(const void* p) {
    unsigned a;
    asm("{ .reg .u64 t; cvta.to.shared.u64 t, %1; cvt.u32.u64 %0, t; }"
        : "=r"(a) : "l"(p));
    return a;
}
#define LDSM4(r, addr) \
    asm volatile("ldmatrix.sync.aligned.m8n8.x4.shared.b16 {%0,%1,%2,%3}, [%4];" \
        : "=r"((r)[0]), "=r"((r)[1]), "=r"((r)[2]), "=r"((r)[3]) : "r"(addr))
#define MMA16816(d, a, b0r, b1r) \
    asm volatile("mma.sync.aligned.m16n8k16.row.col.f32.f16.f16.f32 " \
        "{%0,%1,%2,%3}, {%4,%5,%6,%7}, {%8,%9}, {%0,%1,%2,%3};" \
        : "+f"((d)[0]), "+f"((d)[1]), "+f"((d)[2]), "+f"((d)[3]) \
        : "r"((a)[0]), "r"((a)[1]), "r"((a)[2]), "r"((a)[3]), \
          "r"(b0r), "r"(b1r))
__device__ __forceinline__ unsigned pack_h2(float x, float y) {
    __half2 t = __floats2half2_rn(x, y);
    return *(unsigned*)&t;
}
__device__ __forceinline__ unsigned pack_hh(__half x, __half y) {
    __half2 t = __halves2half2(x, y);
    return *(unsigned*)&t;
}

// ---------------------------------------------------------------------------
// persistent scratch — B operands in direct MMA-fragment layout
// ---------------------------------------------------------------------------
// g_B2: [p][s(8)][wx(4)][ks2(2)][t(4)][lane(32)] x uint4 (one B fragment pair
//       per lane: regs for the two n8 subtiles of an n16 tile, k16 window)
__device__ __align__(16) uint4 g_B2[PPARTS * 8 * 4 * 2 * 4 * 32];   // 786KB
// g_B3: [p][split(2: hi,lo)][nh(2)][ks(16)][lane(32)] x uint4
__device__ __align__(16) uint4 g_B3[PPARTS * 2 * 2 * 16 * 32];      // 196KB
__device__ __align__(16) float g_W1r  [PPARTS * 9 * 256];
__device__ __align__(16) float g_b1eff[PPARTS * 256];
__device__ __align__(16) float g_b3   [PPARTS * 32];

// ---------------------------------------------------------------------------
// prep kernels
// ---------------------------------------------------------------------------
__global__ void prep_small(const float* __restrict__ W1, const float* __restrict__ b1,
                           const float* __restrict__ b3, const float* __restrict__ bocc,
                           const float* __restrict__ frame) {
    int p = blockIdx.x, d = threadIdx.x;
    const int rows[9] = {0, 1, 2, 11, 12, 13, 14, 15, 16};
    float be = b1[p * 256 + d];
#pragma unroll
    for (int f = 0; f < 8; ++f)
        be += frame[f] * W1[(p * 17 + 3 + f) * 256 + d];
    g_b1eff[p * 256 + d] = be;
#pragma unroll
    for (int i = 0; i < 9; ++i)
        g_W1r[(p * 9 + i) * 256 + d] = W1[(p * 17 + rows[i]) * 256 + d];
    if (d < 32) {
        float v = 0.f;
        if (d < 20)  v = b3[p * 20 + d];
        if (d == 20) v = bocc[p];
        g_b3[p * 32 + d] = v;
    }
}

// W2 fragments: B[k][n] = W2[p][k][n] (fp16 hi only, single-chain layer2).
// PTX m16n8k16 B fragment, lane l (q=l%4, g=l/4), k16 window k0, n8 tile n0:
//   reg = { B[k0+2q][n0+g], B[k0+2q+1][n0+g] } and { B[k0+8+2q], B[k0+9+2q] }
__global__ void prep_B2(const float* __restrict__ W2) {
    const int p = blockIdx.x, s = blockIdx.y, wx = blockIdx.z;
    const int tid = threadIdx.x;                 // 256
    const int ks2 = tid >> 7, t = (tid >> 5) & 3, lane = tid & 31;
    const int q = lane & 3, g = lane >> 2;
    const int k0 = s * 32 + ks2 * 16;
    const int n0 = wx * 64 + t * 16;
    const float* Wp = W2 + (size_t)p * 256 * 256;

    auto h = [&](int k, int n) { return __float2half_rn(Wp[k * 256 + n]); };
    uint4 v;
    v.x = pack_hh(h(k0 + 2*q,     n0 + g),     h(k0 + 2*q + 1, n0 + g));
    v.y = pack_hh(h(k0 + 8 + 2*q, n0 + g),     h(k0 + 9 + 2*q, n0 + g));
    v.z = pack_hh(h(k0 + 2*q,     n0 + 8 + g), h(k0 + 2*q + 1, n0 + 8 + g));
    v.w = pack_hh(h(k0 + 8 + 2*q, n0 + 8 + g), h(k0 + 9 + 2*q, n0 + 8 + g));
    g_B2[((((size_t)(p * 8 + s) * 4 + wx) * 2 + ks2) * 4 + t) * 32 + lane] = v;
}

// W3 fragments: B3[k][r] = [W3|Wocc|0]^T, hi and lo splits.
__global__ void prep_B3(const float* __restrict__ W3,
                        const float* __restrict__ Wocc) {
    const int p = blockIdx.x, ks = blockIdx.y;
    const int tid = threadIdx.x;                 // 128
    const int split = tid >> 6, nh = (tid >> 5) & 1, lane = tid & 31;
    const int q = lane & 3, g = lane >> 2;
    const int k0 = ks * 16, n0 = nh * 16;

    auto hv = [&](int k, int r) {
        float w = 0.f;
        if (r < 20)  w = W3[((size_t)(p * 256 + k)) * 20 + r];
        if (r == 20) w = Wocc[(size_t)p * 256 + k];
        __half hi = __float2half_rn(w);
        if (split == 0) return hi;
        return __float2half_rn(w - __half2float(hi));
    };
    uint4 v;
    v.x = pack_hh(hv(k0 + 2*q,     n0 + g),     hv(k0 + 2*q + 1, n0 + g));
    v.y = pack_hh(hv(k0 + 8 + 2*q, n0 + g),     hv(k0 + 9 + 2*q, n0 + g));
    v.z = pack_hh(hv(k0 + 2*q,     n0 + 8 + g), hv(k0 + 2*q + 1, n0 + 8 + g));
    v.w = pack_hh(hv(k0 + 8 + 2*q, n0 + 8 + g), hv(k0 + 9 + 2*q, n0 + 8 + g));
    g_B3[(((size_t)(p * 2 + split) * 2 + nh) * 16 + ks) * 32 + lane] = v;
}

// ---------------------------------------------------------------------------
// main fused kernel
// ---------------------------------------------------------------------------
__global__ void __launch_bounds__(THREADS, 2)
fused_kernel(const float* __restrict__ tpts,
             const float* __restrict__ bigpts,
             const float* __restrict__ viewdir,
             const float* __restrict__ b2g,
             const int* __restrict__ tflag,
             float* __restrict__ out) {
    extern __shared__ unsigned char smc[];
    const int tid  = threadIdx.x;
    const int lane = tid & 31;
    const int wid  = tid >> 5;
    const int wy   = wid >> 2;          // layer2: m tile of 32
    const int wx   = wid & 3;           // layer2: n tile of 64
    const int n0   = blockIdx.x * TM;

    const unsigned sb = smem_to_u32(smc);

    // ---- layer2 A ldmatrix bases (validated R6-R11) ----
    unsigned a_rb[2], a_msk[2];
#pragma unroll
    for (int mt = 0; mt < 2; ++mt) {
        int ml = wy * 32 + mt * 16 + (lane & 15);
        a_rb[mt]  = (unsigned)(ml * 512 + (lane >> 4) * 16);
        a_msk[mt] = (unsigned)((ml & 7) << 4);
    }
    // ---- layer3 bases: warp w -> m-tile (w>>1), n-half (w&1) ----
    const int ml3 = (wid >> 1) * 16 + (lane & 15);
    const unsigned a3_rb  = (unsigned)(ml3 * 512 + (lane >> 4) * 16);
    const unsigned a3_msk = (unsigned)((ml3 & 7) << 4);
    const int nh = wid & 1;
    const int r0 = (wid >> 1) * 16 + (lane >> 2);
    const int r1 = r0 + 8;
    const int cbase = nh * 16 + (lane & 3) * 2;

    float sums[2][4];
#pragma unroll
    for (int t = 0; t < 2; ++t)
#pragma unroll
        for (int q = 0; q < 4; ++q) sums[t][q] = 0.f;

    for (int p = 0; p < PPARTS; ++p) {
        // ---------------- layer 1 (thread = (m, d-chunk of 64)) ----------
        {
            const int m1 = tid & 63;
            const int dc = tid >> 6;
            const int gi = (n0 + m1) * PPARTS + p;
            float x[9];
            x[0] = tpts[gi*3];    x[1] = tpts[gi*3+1];    x[2] = tpts[gi*3+2];
            x[3] = bigpts[gi*3];  x[4] = bigpts[gi*3+1];  x[5] = bigpts[gi*3+2];
            x[6] = viewdir[gi*3]; x[7] = viewdir[gi*3+1]; x[8] = viewdir[gi*3+2];
            const float* w1  = g_W1r + p * 2304;
            const float* b1e = g_b1eff + p * 256;
            const unsigned amask = (unsigned)((m1 & 7) << 4);
            const unsigned mrow  = (unsigned)(m1 * 512 + dc * 128);
#pragma unroll 4
            for (int gq = 0; gq < 16; ++gq) {
                const int d = dc * 64 + gq * 4;
                float4 a = *(const float4*)(b1e + d);
#pragma unroll
                for (int i = 0; i < 9; ++i) {
                    float4 w = *(const float4*)(w1 + i * 256 + d);
                    a.x += x[i]*w.x; a.y += x[i]*w.y;
                    a.z += x[i]*w.z; a.w += x[i]*w.w;
                }
                a.x = fmaxf(a.x, 0.f); a.y = fmaxf(a.y, 0.f);
                a.z = fmaxf(a.z, 0.f); a.w = fmaxf(a.w, 0.f);
                unsigned o0 = (mrow + gq * 8) ^ amask;
                unsigned o1 = (mrow + gq * 8 + 4) ^ amask;
                *(unsigned*)(smc + OFF_AHI + o0) = pack_h2(a.x, a.y);
                *(unsigned*)(smc + OFF_AHI + o1) = pack_h2(a.z, a.w);
            }
        }
        __syncthreads();   // (1) A plane ready CTA-wide

        // ---------------- layer 2: barrier-free, B via __ldg -------------
        float acc[2][8][4];
#pragma unroll
        for (int mt = 0; mt < 2; ++mt)
#pragma unroll
            for (int nt = 0; nt < 8; ++nt)
#pragma unroll
                for (int q = 0; q < 4; ++q) acc[mt][nt][q] = 0.f;

#pragma unroll 1
        for (int s = 0; s < 8; ++s) {
            const uint4* bsrc = g_B2 + ((size_t)((p * 8 + s) * 4 + wx)) * 256;
#pragma unroll
            for (int ks2 = 0; ks2 < 2; ++ks2) {
                const unsigned cc = (unsigned)(s * 64 + ks2 * 32);
                unsigned ah[2][4];
                uint4 bb[4];
#pragma unroll
                for (int t = 0; t < 4; ++t)
                    bb[t] = __ldg(bsrc + (ks2 * 4 + t) * 32 + lane);
                LDSM4(ah[0], sb + OFF_AHI + ((a_rb[0] + cc) ^ a_msk[0]));
                LDSM4(ah[1], sb + OFF_AHI + ((a_rb[1] + cc) ^ a_msk[1]));
#pragma unroll
                for (int mt = 0; mt < 2; ++mt)
#pragma unroll
                    for (int t = 0; t < 4; ++t) {
                        MMA16816(acc[mt][2*t],   ah[mt], bb[t].x, bb[t].y);
                        MMA16816(acc[mt][2*t+1], ah[mt], bb[t].z, bb[t].w);
                    }
            }
        }
        __syncthreads();   // (2) all layer2 A-plane reads done

        // ---------------- epilogue: acc -> h2 fp16 hi/lo planes ----------
#pragma unroll
        for (int mt = 0; mt < 2; ++mt) {
            const int row0 = wy * 32 + mt * 16 + (lane >> 2);
#pragma unroll
            for (int nt = 0; nt < 8; ++nt) {
                const int e = wx * 64 + nt * 8 + (lane & 3) * 2;
                float2 bv = *(const float2*)(b2g + p * 256 + e);
                float v0 = fmaxf(acc[mt][nt][0] + bv.x, 0.f);
                float v1 = fmaxf(acc[mt][nt][1] + bv.y, 0.f);
                float v2 = fmaxf(acc[mt][nt][2] + bv.x, 0.f);
                float v3 = fmaxf(acc[mt][nt][3] + bv.y, 0.f);
                float h0 = __half2float(__float2half_rn(v0));
                float h1 = __half2float(__float2half_rn(v1));
                float h2 = __half2float(__float2half_rn(v2));
                float h3 = __half2float(__float2half_rn(v3));
                unsigned o0 = (unsigned)(row0 * 512 + e * 2) ^
                              (unsigned)((row0 & 7) << 4);
                unsigned o1 = (unsigned)((row0 + 8) * 512 + e * 2) ^
                              (unsigned)(((row0 + 8) & 7) << 4);
                *(unsigned*)(smc + OFF_AHI + o0) = pack_h2(v0, v1);
                *(unsigned*)(smc + OFF_ALO + o0) = pack_h2(v0 - h0, v1 - h1);
                *(unsigned*)(smc + OFF_AHI + o1) = pack_h2(v2, v3);
                *(unsigned*)(smc + OFF_ALO + o1) = pack_h2(v2 - h2, v3 - h3);
            }
        }
        __syncthreads();   // (3) h2 planes visible CTA-wide

        // ---------------- layer 3: 3-chain, B via __ldg ------------------
        float acc3[2][4];
#pragma unroll
        for (int t = 0; t < 2; ++t)
#pragma unroll
            for (int q = 0; q < 4; ++q) acc3[t][q] = 0.f;
        {
            const uint4* bhi = g_B3 + ((size_t)((p * 2 + 0) * 2 + nh)) * 16 * 32;
            const uint4* blo = g_B3 + ((size_t)((p * 2 + 1) * 2 + nh)) * 16 * 32;
#pragma unroll 2
            for (int ks = 0; ks < 16; ++ks) {
                const unsigned cc = (unsigned)(ks * 32);
                unsigned ah[4], al[4];
                uint4 bh = __ldg(bhi + ks * 32 + lane);
                uint4 bl = __ldg(blo + ks * 32 + lane);
                LDSM4(ah, sb + OFF_AHI + ((a3_rb + cc) ^ a3_msk));
                LDSM4(al, sb + OFF_ALO + ((a3_rb + cc) ^ a3_msk));
                MMA16816(acc3[0], ah, bh.x, bh.y);
                MMA16816(acc3[1], ah, bh.z, bh.w);
                MMA16816(acc3[0], al, bh.x, bh.y);
                MMA16816(acc3[1], al, bh.z, bh.w);
                MMA16816(acc3[0], ah, bl.x, bl.y);
                MMA16816(acc3[1], ah, bl.z, bl.w);
            }
        }

        // ---------------- extraction: mask, sigmoid, accumulate ----------
        {
            const float fl0 = (tflag[(n0 + r0) * PPARTS + p] != 0) ? 1.f : 0.f;
            const float fl1 = (tflag[(n0 + r1) * PPARTS + p] != 0) ? 1.f : 0.f;
#pragma unroll
            for (int t = 0; t < 2; ++t) {
                const int c = cbase + t * 8;
                const float b3a = g_b3[p * 32 + c];
                const float b3b = g_b3[p * 32 + c + 1];
                float v0 = acc3[t][0] + b3a, v1 = acc3[t][1] + b3b;
                float v2 = acc3[t][2] + b3a, v3 = acc3[t][3] + b3b;
                if (c == 20) {
                    v0 = (1.f / (1.f + __expf(-v0))) * fl0;
                    v2 = (1.f / (1.f + __expf(-v2))) * fl1;
                    out[(size_t)(n0 + r0) * OUTC + 21 + p] = v0;   // tocc
                    out[(size_t)(n0 + r1) * OUTC + 21 + p] = v2;
                } else {
                    v0 *= fl0; v2 *= fl1;
                }
                v1 *= fl0; v3 *= fl1;
                sums[t][0] += v0; sums[t][1] += v1;
                sums[t][2] += v2; sums[t][3] += v3;
            }
        }
        __syncthreads();   // (4) layer3 h2 reads done before next layer1
    }

    // ---------------- final masked means ----------------
    const float inv6 = 1.f / 6.f;
#pragma unroll
    for (int t = 0; t < 2; ++t) {
        const int c = cbase + t * 8;
        if (c < 21) {
            out[(size_t)(n0 + r0) * OUTC + c] = sums[t][0] * inv6;
            out[(size_t)(n0 + r1) * OUTC + c] = sums[t][2] * inv6;
        }
        if (c + 1 < 21) {
            out[(size_t)(n0 + r0) * OUTC + c + 1] = sums[t][1] * inv6;
            out[(size_t)(n0 + r1) * OUTC + c + 1] = sums[t][3] * inv6;
        }
    }
}

// ---------------------------------------------------------------------------
// launch
// ---------------------------------------------------------------------------
extern "C" void kernel_launch(void* const* d_in, const int* in_sizes, int n_in,
                              void* d_out, int out_size) {
    const float* tpts    = (const float*)d_in[0];
    const float* bigpts  = (const float*)d_in[1];
    const float* viewdir = (const float*)d_in[2];
    // d_in[3]=dists, d_in[4]=part_dist unused
    const float* frame   = (const float*)d_in[5];
    const float* W1      = (const float*)d_in[6];
    const float* b1      = (const float*)d_in[7];
    const float* W2      = (const float*)d_in[8];
    const float* b2      = (const float*)d_in[9];
    const float* W3      = (const float*)d_in[10];
    const float* b3      = (const float*)d_in[11];
    const float* Wocc    = (const float*)d_in[12];
    const float* bocc    = (const float*)d_in[13];
    const int*   tflag   = (const int*)d_in[14];
    float* out = (float*)d_out;

    prep_small<<<PPARTS, 256>>>(W1, b1, b3, bocc, frame);
    prep_B2<<<dim3(PPARTS, 8, 4), 256>>>(W2);
    prep_B3<<<dim3(PPARTS, 16), 128>>>(W3, Wocc);

    cudaFuncSetAttribute(fused_kernel,
                         cudaFuncAttributeMaxDynamicSharedMemorySize,
                         SMEM_BYTES);
    fused_kernel<<<NCTAS, THREADS, SMEM_BYTES>>>(tpts, bigpts, viewdir,
                                                 b2, tflag, out);
}

// round 13
// speedup vs baseline: 1.0785x; 1.0785x over previous
#include <cuda_runtime.h>
#include <cuda_fp16.h>

// ---------------------------------------------------------------------------
// TPoseHuman fused 6-part MLP — layers 2 AND 3 on mma.sync fp16.
// R13 = R12 (B operands direct from global in MMA-fragment layout, no smem
// ring) + REGISTER SOFTWARE PIPELINING of the B loads: two-buffer half-stage
// lookahead so LDG latency hides behind MMAs. g_B2 reordered to give a
// uniform per-half-stage stride.
//   layer2: single-chain fp16 (validated rel_err 1.6e-4)
//   layer3: 3-chain hi/lo fp16, one-iteration LDG lookahead
// ---------------------------------------------------------------------------

#define NPTS    65536
#define PPARTS  6
#define TM      64
#define NCTAS   (NPTS / TM)       // 1024
#define THREADS 256
#define OUTC    27

// ---- smem byte offsets (A/h2 planes only) ----
#define OFF_AHI  0u               // 64 rows x 512B (A hi / h2 hi)
#define OFF_ALO  32768u           // 64 rows x 512B (h2 lo, layer3 only)
#define SMEM_BYTES 65536

// ---------------------------------------------------------------------------
// asm helpers (baseline PTX, sm_80-era: family-safe on compute_103)
// ---------------------------------------------------------------------------
__device__ __forceinline__ unsigned smem_to_u32(const void* p) {
    unsigned a;
    asm("{ .reg .u64 t; cvta.to.shared.u64 t, %1; cvt.u32.u64 %0, t; }"
        : "=r"(a) : "l"(p));
    return a;
}
#define LDSM4(r, addr) \
    asm volatile("ldmatrix.sync.aligned.m8n8.x4.shared.b16 {%0,%1,%2,%3}, [%4];" \
        : "=r"((r)[0]), "=r"((r)[1]), "=r"((r)[2]), "=r"((r)[3]) : "r"(addr))
#define MMA16816(d, a, b0r, b1r) \
    asm volatile("mma.sync.aligned.m16n8k16.row.col.f32.f16.f16.f32 " \
        "{%0,%1,%2,%3}, {%4,%5,%6,%7}, {%8,%9}, {%0,%1,%2,%3};" \
        : "+f"((d)[0]), "+f"((d)[1]), "+f"((d)[2]), "+f"((d)[3]) \
        : "r"((a)[0]), "r"((a)[1]), "r"((a)[2]), "r"((a)[3]), \
          "r"(b0r), "r"(b1r))
__device__ __forceinline__ unsigned pack_h2(float x, float y) {
    __half2 t = __floats2half2_rn(x, y);
    return *(unsigned*)&t;
}
__device__ __forceinline__ unsigned pack_hh(__half x, __half y) {
    __half2 t = __halves2half2(x, y);
    return *(unsigned*)&t;
}

// ---------------------------------------------------------------------------
// persistent scratch — B operands in direct MMA-fragment layout
// ---------------------------------------------------------------------------
// g_B2: [p][wx(4)][hs(16)][t(4)][lane(32)] x uint4 — uniform 128-uint4 stride
// per half-stage for register pipelining.
__device__ __align__(16) uint4 g_B2[PPARTS * 4 * 16 * 4 * 32];      // 786KB
// g_B3: [p][split(2: hi,lo)][nh(2)][ks(16)][lane(32)] x uint4
__device__ __align__(16) uint4 g_B3[PPARTS * 2 * 2 * 16 * 32];      // 196KB
__device__ __align__(16) float g_W1r  [PPARTS * 9 * 256];
__device__ __align__(16) float g_b1eff[PPARTS * 256];
__device__ __align__(16) float g_b3   [PPARTS * 32];

// ---------------------------------------------------------------------------
// prep kernels
// ---------------------------------------------------------------------------
__global__ void prep_small(const float* __restrict__ W1, const float* __restrict__ b1,
                           const float* __restrict__ b3, const float* __restrict__ bocc,
                           const float* __restrict__ frame) {
    int p = blockIdx.x, d = threadIdx.x;
    const int rows[9] = {0, 1, 2, 11, 12, 13, 14, 15, 16};
    float be = b1[p * 256 + d];
#pragma unroll
    for (int f = 0; f < 8; ++f)
        be += frame[f] * W1[(p * 17 + 3 + f) * 256 + d];
    g_b1eff[p * 256 + d] = be;
#pragma unroll
    for (int i = 0; i < 9; ++i)
        g_W1r[(p * 9 + i) * 256 + d] = W1[(p * 17 + rows[i]) * 256 + d];
    if (d < 32) {
        float v = 0.f;
        if (d < 20)  v = b3[p * 20 + d];
        if (d == 20) v = bocc[p];
        g_b3[p * 32 + d] = v;
    }
}

// W2 fragments (layout validated in R12 by exact rel_err match):
// PTX m16n8k16 B fragment, lane l (q=l%4, g=l/4), k16 window k0, n8 tile n0:
//   regs = { B[k0+2q][n0+g], B[k0+2q+1][n0+g] }, { B[k0+8+2q], B[k0+9+2q] }
__global__ void prep_B2(const float* __restrict__ W2) {
    const int p = blockIdx.x, s = blockIdx.y, wx = blockIdx.z;
    const int tid = threadIdx.x;                 // 256
    const int ks2 = tid >> 7, t = (tid >> 5) & 3, lane = tid & 31;
    const int q = lane & 3, g = lane >> 2;
    const int hs = s * 2 + ks2;
    const int k0 = hs * 16;
    const int n0 = wx * 64 + t * 16;
    const float* Wp = W2 + (size_t)p * 256 * 256;

    auto h = [&](int k, int n) { return __float2half_rn(Wp[k * 256 + n]); };
    uint4 v;
    v.x = pack_hh(h(k0 + 2*q,     n0 + g),     h(k0 + 2*q + 1, n0 + g));
    v.y = pack_hh(h(k0 + 8 + 2*q, n0 + g),     h(k0 + 9 + 2*q, n0 + g));
    v.z = pack_hh(h(k0 + 2*q,     n0 + 8 + g), h(k0 + 2*q + 1, n0 + 8 + g));
    v.w = pack_hh(h(k0 + 8 + 2*q, n0 + 8 + g), h(k0 + 9 + 2*q, n0 + 8 + g));
    g_B2[(((size_t)(p * 4 + wx) * 16 + hs) * 4 + t) * 32 + lane] = v;
}

// W3 fragments: B3[k][r] = [W3|Wocc|0]^T, hi and lo splits.
__global__ void prep_B3(const float* __restrict__ W3,
                        const float* __restrict__ Wocc) {
    const int p = blockIdx.x, ks = blockIdx.y;
    const int tid = threadIdx.x;                 // 128
    const int split = tid >> 6, nh = (tid >> 5) & 1, lane = tid & 31;
    const int q = lane & 3, g = lane >> 2;
    const int k0 = ks * 16, n0 = nh * 16;

    auto hv = [&](int k, int r) {
        float w = 0.f;
        if (r < 20)  w = W3[((size_t)(p * 256 + k)) * 20 + r];
        if (r == 20) w = Wocc[(size_t)p * 256 + k];
        __half hi = __float2half_rn(w);
        if (split == 0) return hi;
        return __float2half_rn(w - __half2float(hi));
    };
    uint4 v;
    v.x = pack_hh(hv(k0 + 2*q,     n0 + g),     hv(k0 + 2*q + 1, n0 + g));
    v.y = pack_hh(hv(k0 + 8 + 2*q, n0 + g),     hv(k0 + 9 + 2*q, n0 + g));
    v.z = pack_hh(hv(k0 + 2*q,     n0 + 8 + g), hv(k0 + 2*q + 1, n0 + 8 + g));
    v.w = pack_hh(hv(k0 + 8 + 2*q, n0 + 8 + g), hv(k0 + 9 + 2*q, n0 + 8 + g));
    g_B3[(((size_t)(p * 2 + split) * 2 + nh) * 16 + ks) * 32 + lane] = v;
}

// ---------------------------------------------------------------------------
// main fused kernel
// ---------------------------------------------------------------------------
__global__ void __launch_bounds__(THREADS, 2)
fused_kernel(const float* __restrict__ tpts,
             const float* __restrict__ bigpts,
             const float* __restrict__ viewdir,
             const float* __restrict__ b2g,
             const int* __restrict__ tflag,
             float* __restrict__ out) {
    extern __shared__ unsigned char smc[];
    const int tid  = threadIdx.x;
    const int lane = tid & 31;
    const int wid  = tid >> 5;
    const int wy   = wid >> 2;          // layer2: m tile of 32
    const int wx   = wid & 3;           // layer2: n tile of 64
    const int n0   = blockIdx.x * TM;

    const unsigned sb = smem_to_u32(smc);

    // ---- layer2 A ldmatrix bases (validated R6-R12) ----
    unsigned a_rb[2], a_msk[2];
#pragma unroll
    for (int mt = 0; mt < 2; ++mt) {
        int ml = wy * 32 + mt * 16 + (lane & 15);
        a_rb[mt]  = (unsigned)(ml * 512 + (lane >> 4) * 16);
        a_msk[mt] = (unsigned)((ml & 7) << 4);
    }
    // ---- layer3 bases: warp w -> m-tile (w>>1), n-half (w&1) ----
    const int ml3 = (wid >> 1) * 16 + (lane & 15);
    const unsigned a3_rb  = (unsigned)(ml3 * 512 + (lane >> 4) * 16);
    const unsigned a3_msk = (unsigned)((ml3 & 7) << 4);
    const int nh = wid & 1;
    const int r0 = (wid >> 1) * 16 + (lane >> 2);
    const int r1 = r0 + 8;
    const int cbase = nh * 16 + (lane & 3) * 2;

    float sums[2][4];
#pragma unroll
    for (int t = 0; t < 2; ++t)
#pragma unroll
        for (int q = 0; q < 4; ++q) sums[t][q] = 0.f;

    for (int p = 0; p < PPARTS; ++p) {
        const uint4* bbase = g_B2 + (size_t)(p * 4 + wx) * 2048 + lane;

        // prefetch first half-stage's B fragments (hides behind layer1+bar)
        uint4 b0[4], b1[4];
#pragma unroll
        for (int t = 0; t < 4; ++t) b0[t] = __ldg(bbase + t * 32);

        // ---------------- layer 1 (thread = (m, d-chunk of 64)) ----------
        {
            const int m1 = tid & 63;
            const int dc = tid >> 6;
            const int gi = (n0 + m1) * PPARTS + p;
            float x[9];
            x[0] = tpts[gi*3];    x[1] = tpts[gi*3+1];    x[2] = tpts[gi*3+2];
            x[3] = bigpts[gi*3];  x[4] = bigpts[gi*3+1];  x[5] = bigpts[gi*3+2];
            x[6] = viewdir[gi*3]; x[7] = viewdir[gi*3+1]; x[8] = viewdir[gi*3+2];
            const float* w1  = g_W1r + p * 2304;
            const float* b1e = g_b1eff + p * 256;
            const unsigned amask = (unsigned)((m1 & 7) << 4);
            const unsigned mrow  = (unsigned)(m1 * 512 + dc * 128);
#pragma unroll 4
            for (int gq = 0; gq < 16; ++gq) {
                const int d = dc * 64 + gq * 4;
                float4 a = *(const float4*)(b1e + d);
#pragma unroll
                for (int i = 0; i < 9; ++i) {
                    float4 w = *(const float4*)(w1 + i * 256 + d);
                    a.x += x[i]*w.x; a.y += x[i]*w.y;
                    a.z += x[i]*w.z; a.w += x[i]*w.w;
                }
                a.x = fmaxf(a.x, 0.f); a.y = fmaxf(a.y, 0.f);
                a.z = fmaxf(a.z, 0.f); a.w = fmaxf(a.w, 0.f);
                unsigned o0 = (mrow + gq * 8) ^ amask;
                unsigned o1 = (mrow + gq * 8 + 4) ^ amask;
                *(unsigned*)(smc + OFF_AHI + o0) = pack_h2(a.x, a.y);
                *(unsigned*)(smc + OFF_AHI + o1) = pack_h2(a.z, a.w);
            }
        }
        __syncthreads();   // (1) A plane ready CTA-wide

        // ---------------- layer 2: reg-pipelined B, barrier-free ---------
        float acc[2][8][4];
#pragma unroll
        for (int mt = 0; mt < 2; ++mt)
#pragma unroll
            for (int nt = 0; nt < 8; ++nt)
#pragma unroll
                for (int q = 0; q < 4; ++q) acc[mt][nt][q] = 0.f;

#pragma unroll 1
        for (int hs = 0; hs < 16; hs += 2) {
            // in-flight: load hs+1 while computing hs
#pragma unroll
            for (int t = 0; t < 4; ++t)
                b1[t] = __ldg(bbase + (hs + 1) * 128 + t * 32);
            {
                const unsigned cc = (unsigned)(hs * 32);
                unsigned ah[2][4];
                LDSM4(ah[0], sb + OFF_AHI + ((a_rb[0] + cc) ^ a_msk[0]));
                LDSM4(ah[1], sb + OFF_AHI + ((a_rb[1] + cc) ^ a_msk[1]));
#pragma unroll
                for (int mt = 0; mt < 2; ++mt)
#pragma unroll
                    for (int t = 0; t < 4; ++t) {
                        MMA16816(acc[mt][2*t],   ah[mt], b0[t].x, b0[t].y);
                        MMA16816(acc[mt][2*t+1], ah[mt], b0[t].z, b0[t].w);
                    }
            }
            // load hs+2 while computing hs+1
            if (hs + 2 < 16) {
#pragma unroll
                for (int t = 0; t < 4; ++t)
                    b0[t] = __ldg(bbase + (hs + 2) * 128 + t * 32);
            }
            {
                const unsigned cc = (unsigned)(hs * 32 + 32);
                unsigned ah[2][4];
                LDSM4(ah[0], sb + OFF_AHI + ((a_rb[0] + cc) ^ a_msk[0]));
                LDSM4(ah[1], sb + OFF_AHI + ((a_rb[1] + cc) ^ a_msk[1]));
#pragma unroll
                for (int mt = 0; mt < 2; ++mt)
#pragma unroll
                    for (int t = 0; t < 4; ++t) {
                        MMA16816(acc[mt][2*t],   ah[mt], b1[t].x, b1[t].y);
                        MMA16816(acc[mt][2*t+1], ah[mt], b1[t].z, b1[t].w);
                    }
            }
        }
        __syncthreads();   // (2) all layer2 A-plane reads done

        // ---------------- epilogue: acc -> h2 fp16 hi/lo planes ----------
#pragma unroll
        for (int mt = 0; mt < 2; ++mt) {
            const int row0 = wy * 32 + mt * 16 + (lane >> 2);
#pragma unroll
            for (int nt = 0; nt < 8; ++nt) {
                const int e = wx * 64 + nt * 8 + (lane & 3) * 2;
                float2 bv = *(const float2*)(b2g + p * 256 + e);
                float v0 = fmaxf(acc[mt][nt][0] + bv.x, 0.f);
                float v1 = fmaxf(acc[mt][nt][1] + bv.y, 0.f);
                float v2 = fmaxf(acc[mt][nt][2] + bv.x, 0.f);
                float v3 = fmaxf(acc[mt][nt][3] + bv.y, 0.f);
                float h0 = __half2float(__float2half_rn(v0));
                float h1 = __half2float(__float2half_rn(v1));
                float h2 = __half2float(__float2half_rn(v2));
                float h3 = __half2float(__float2half_rn(v3));
                unsigned o0 = (unsigned)(row0 * 512 + e * 2) ^
                              (unsigned)((row0 & 7) << 4);
                unsigned o1 = (unsigned)((row0 + 8) * 512 + e * 2) ^
                              (unsigned)(((row0 + 8) & 7) << 4);
                *(unsigned*)(smc + OFF_AHI + o0) = pack_h2(v0, v1);
                *(unsigned*)(smc + OFF_ALO + o0) = pack_h2(v0 - h0, v1 - h1);
                *(unsigned*)(smc + OFF_AHI + o1) = pack_h2(v2, v3);
                *(unsigned*)(smc + OFF_ALO + o1) = pack_h2(v2 - h2, v3 - h3);
            }
        }
        __syncthreads();   // (3) h2 planes visible CTA-wide

        // ---------------- layer 3: 3-chain, pipelined B via __ldg --------
        float acc3[2][4];
#pragma unroll
        for (int t = 0; t < 2; ++t)
#pragma unroll
            for (int q = 0; q < 4; ++q) acc3[t][q] = 0.f;
        {
            const uint4* bhi = g_B3 + ((size_t)((p * 2 + 0) * 2 + nh)) * 512 + lane;
            const uint4* blo = g_B3 + ((size_t)((p * 2 + 1) * 2 + nh)) * 512 + lane;
            uint4 bh = __ldg(bhi), bl = __ldg(blo);
#pragma unroll 1
            for (int ks = 0; ks < 16; ++ks) {
                uint4 bhc = bh, blc = bl;
                if (ks + 1 < 16) {
                    bh = __ldg(bhi + (ks + 1) * 32);
                    bl = __ldg(blo + (ks + 1) * 32);
                }
                const unsigned cc = (unsigned)(ks * 32);
                unsigned ah[4], al[4];
                LDSM4(ah, sb + OFF_AHI + ((a3_rb + cc) ^ a3_msk));
                LDSM4(al, sb + OFF_ALO + ((a3_rb + cc) ^ a3_msk));
                MMA16816(acc3[0], ah, bhc.x, bhc.y);
                MMA16816(acc3[1], ah, bhc.z, bhc.w);
                MMA16816(acc3[0], al, bhc.x, bhc.y);
                MMA16816(acc3[1], al, bhc.z, bhc.w);
                MMA16816(acc3[0], ah, blc.x, blc.y);
                MMA16816(acc3[1], ah, blc.z, blc.w);
            }
        }

        // ---------------- extraction: mask, sigmoid, accumulate ----------
        {
            const float fl0 = (tflag[(n0 + r0) * PPARTS + p] != 0) ? 1.f : 0.f;
            const float fl1 = (tflag[(n0 + r1) * PPARTS + p] != 0) ? 1.f : 0.f;
#pragma unroll
            for (int t = 0; t < 2; ++t) {
                const int c = cbase + t * 8;
                const float b3a = g_b3[p * 32 + c];
                const float b3b = g_b3[p * 32 + c + 1];
                float v0 = acc3[t][0] + b3a, v1 = acc3[t][1] + b3b;
                float v2 = acc3[t][2] + b3a, v3 = acc3[t][3] + b3b;
                if (c == 20) {
                    v0 = (1.f / (1.f + __expf(-v0))) * fl0;
                    v2 = (1.f / (1.f + __expf(-v2))) * fl1;
                    out[(size_t)(n0 + r0) * OUTC + 21 + p] = v0;   // tocc
                    out[(size_t)(n0 + r1) * OUTC + 21 + p] = v2;
                } else {
                    v0 *= fl0; v2 *= fl1;
                }
                v1 *= fl0; v3 *= fl1;
                sums[t][0] += v0; sums[t][1] += v1;
                sums[t][2] += v2; sums[t][3] += v3;
            }
        }
        __syncthreads();   // (4) layer3 h2 reads done before next layer1
    }

    // ---------------- final masked means ----------------
    const float inv6 = 1.f / 6.f;
#pragma unroll
    for (int t = 0; t < 2; ++t) {
        const int c = cbase + t * 8;
        if (c < 21) {
            out[(size_t)(n0 + r0) * OUTC + c] = sums[t][0] * inv6;
            out[(size_t)(n0 + r1) * OUTC + c] = sums[t][2] * inv6;
        }
        if (c + 1 < 21) {
            out[(size_t)(n0 + r0) * OUTC + c + 1] = sums[t][1] * inv6;
            out[(size_t)(n0 + r1) * OUTC + c + 1] = sums[t][3] * inv6;
        }
    }
}

// ---------------------------------------------------------------------------
// launch
// ---------------------------------------------------------------------------
extern "C" void kernel_launch(void* const* d_in, const int* in_sizes, int n_in,
                              void* d_out, int out_size) {
    const float* tpts    = (const float*)d_in[0];
    const float* bigpts  = (const float*)d_in[1];
    const float* viewdir = (const float*)d_in[2];
    // d_in[3]=dists, d_in[4]=part_dist unused
    const float* frame   = (const float*)d_in[5];
    const float* W1      = (const float*)d_in[6];
    const float* b1      = (const float*)d_in[7];
    const float* W2      = (const float*)d_in[8];
    const float* b2      = (const float*)d_in[9];
    const float* W3      = (const float*)d_in[10];
    const float* b3      = (const float*)d_in[11];
    const float* Wocc    = (const float*)d_in[12];
    const float* bocc    = (const float*)d_in[13];
    const int*   tflag   = (const int*)d_in[14];
    float* out = (float*)d_out;

    prep_small<<<PPARTS, 256>>>(W1, b1, b3, bocc, frame);
    prep_B2<<<dim3(PPARTS, 8, 4), 256>>>(W2);
    prep_B3<<<dim3(PPARTS, 16), 128>>>(W3, Wocc);

    cudaFuncSetAttribute(fused_kernel,
                         cudaFuncAttributeMaxDynamicSharedMemorySize,
                         SMEM_BYTES);
    fused_kernel<<<NCTAS, THREADS, SMEM_BYTES>>>(tpts, bigpts, viewdir,
                                                 b2, tflag, out);
}

// round 14
// speedup vs baseline: 1.0805x; 1.0019x over previous
#include <cuda_runtime.h>
#include <cuda_fp16.h>

// ---------------------------------------------------------------------------
// TPoseHuman fused 6-part MLP — layers 2 AND 3 on mma.sync fp16.
// R14 = R13 (B direct from global in MMA-fragment layout, register-pipelined)
//  + layer3 single-chain fp16 (error budget validated: adds ~2 x 1.2e-4 terms)
//  + h2 in its own smem plane (no WAR with A plane -> one fewer CTA barrier)
// ---------------------------------------------------------------------------

#define NPTS    65536
#define PPARTS  6
#define TM      64
#define NCTAS   (NPTS / TM)       // 1024
#define THREADS 256
#define OUTC    27

// ---- smem byte offsets ----
#define OFF_AHI  0u               // 64 rows x 512B : layer1 A-hi plane
#define OFF_H2   32768u           // 64 rows x 512B : h2 fp16 plane (layer3 A)
#define SMEM_BYTES 65536

// ---------------------------------------------------------------------------
// asm helpers (baseline PTX, sm_80-era: family-safe on compute_103)
// ---------------------------------------------------------------------------
__device__ __forceinline__ unsigned smem_to_u32(const void* p) {
    unsigned a;
    asm("{ .reg .u64 t; cvta.to.shared.u64 t, %1; cvt.u32.u64 %0, t; }"
        : "=r"(a) : "l"(p));
    return a;
}
#define LDSM4(r, addr) \
    asm volatile("ldmatrix.sync.aligned.m8n8.x4.shared.b16 {%0,%1,%2,%3}, [%4];" \
        : "=r"((r)[0]), "=r"((r)[1]), "=r"((r)[2]), "=r"((r)[3]) : "r"(addr))
#define MMA16816(d, a, b0r, b1r) \
    asm volatile("mma.sync.aligned.m16n8k16.row.col.f32.f16.f16.f32 " \
        "{%0,%1,%2,%3}, {%4,%5,%6,%7}, {%8,%9}, {%0,%1,%2,%3};" \
        : "+f"((d)[0]), "+f"((d)[1]), "+f"((d)[2]), "+f"((d)[3]) \
        : "r"((a)[0]), "r"((a)[1]), "r"((a)[2]), "r"((a)[3]), \
          "r"(b0r), "r"(b1r))
__device__ __forceinline__ unsigned pack_h2(float x, float y) {
    __half2 t = __floats2half2_rn(x, y);
    return *(unsigned*)&t;
}
__device__ __forceinline__ unsigned pack_hh(__half x, __half y) {
    __half2 t = __halves2half2(x, y);
    return *(unsigned*)&t;
}

// ---------------------------------------------------------------------------
// persistent scratch — B operands in direct MMA-fragment layout
// ---------------------------------------------------------------------------
// g_B2: [p][wx(4)][hs(16)][t(4)][lane(32)] x uint4 — uniform 128-uint4 stride
__device__ __align__(16) uint4 g_B2[PPARTS * 4 * 16 * 4 * 32];      // 786KB
// g_B3: [p][nh(2)][ks(16)][lane(32)] x uint4 (hi split only)
__device__ __align__(16) uint4 g_B3[PPARTS * 2 * 16 * 32];          // 98KB
__device__ __align__(16) float g_W1r  [PPARTS * 9 * 256];
__device__ __align__(16) float g_b1eff[PPARTS * 256];
__device__ __align__(16) float g_b3   [PPARTS * 32];

// ---------------------------------------------------------------------------
// prep kernels
// ---------------------------------------------------------------------------
__global__ void prep_small(const float* __restrict__ W1, const float* __restrict__ b1,
                           const float* __restrict__ b3, const float* __restrict__ bocc,
                           const float* __restrict__ frame) {
    int p = blockIdx.x, d = threadIdx.x;
    const int rows[9] = {0, 1, 2, 11, 12, 13, 14, 15, 16};
    float be = b1[p * 256 + d];
#pragma unroll
    for (int f = 0; f < 8; ++f)
        be += frame[f] * W1[(p * 17 + 3 + f) * 256 + d];
    g_b1eff[p * 256 + d] = be;
#pragma unroll
    for (int i = 0; i < 9; ++i)
        g_W1r[(p * 9 + i) * 256 + d] = W1[(p * 17 + rows[i]) * 256 + d];
    if (d < 32) {
        float v = 0.f;
        if (d < 20)  v = b3[p * 20 + d];
        if (d == 20) v = bocc[p];
        g_b3[p * 32 + d] = v;
    }
}

// W2 fragments (layout validated R12/R13 by exact rel_err match):
// PTX m16n8k16 B fragment, lane l (q=l%4, g=l/4), k16 window k0, n8 tile n0:
//   regs = { B[k0+2q][n0+g], B[k0+2q+1][n0+g] }, { B[k0+8+2q], B[k0+9+2q] }
__global__ void prep_B2(const float* __restrict__ W2) {
    const int p = blockIdx.x, s = blockIdx.y, wx = blockIdx.z;
    const int tid = threadIdx.x;                 // 256
    const int ks2 = tid >> 7, t = (tid >> 5) & 3, lane = tid & 31;
    const int q = lane & 3, g = lane >> 2;
    const int hs = s * 2 + ks2;
    const int k0 = hs * 16;
    const int n0 = wx * 64 + t * 16;
    const float* Wp = W2 + (size_t)p * 256 * 256;

    auto h = [&](int k, int n) { return __float2half_rn(Wp[k * 256 + n]); };
    uint4 v;
    v.x = pack_hh(h(k0 + 2*q,     n0 + g),     h(k0 + 2*q + 1, n0 + g));
    v.y = pack_hh(h(k0 + 8 + 2*q, n0 + g),     h(k0 + 9 + 2*q, n0 + g));
    v.z = pack_hh(h(k0 + 2*q,     n0 + 8 + g), h(k0 + 2*q + 1, n0 + 8 + g));
    v.w = pack_hh(h(k0 + 8 + 2*q, n0 + 8 + g), h(k0 + 9 + 2*q, n0 + 8 + g));
    g_B2[(((size_t)(p * 4 + wx) * 16 + hs) * 4 + t) * 32 + lane] = v;
}

// W3 fragments: B3[k][r] = [W3|Wocc|0]^T, fp16 hi only (single-chain layer3)
__global__ void prep_B3(const float* __restrict__ W3,
                        const float* __restrict__ Wocc) {
    const int p = blockIdx.x, ks = blockIdx.y;
    const int tid = threadIdx.x;                 // 64
    const int nh = tid >> 5, lane = tid & 31;
    const int q = lane & 3, g = lane >> 2;
    const int k0 = ks * 16, n0 = nh * 16;

    auto hv = [&](int k, int r) {
        float w = 0.f;
        if (r < 20)  w = W3[((size_t)(p * 256 + k)) * 20 + r];
        if (r == 20) w = Wocc[(size_t)p * 256 + k];
        return __float2half_rn(w);
    };
    uint4 v;
    v.x = pack_hh(hv(k0 + 2*q,     n0 + g),     hv(k0 + 2*q + 1, n0 + g));
    v.y = pack_hh(hv(k0 + 8 + 2*q, n0 + g),     hv(k0 + 9 + 2*q, n0 + g));
    v.z = pack_hh(hv(k0 + 2*q,     n0 + 8 + g), hv(k0 + 2*q + 1, n0 + 8 + g));
    v.w = pack_hh(hv(k0 + 8 + 2*q, n0 + 8 + g), hv(k0 + 9 + 2*q, n0 + 8 + g));
    g_B3[(((size_t)(p * 2 + nh)) * 16 + ks) * 32 + lane] = v;
}

// ---------------------------------------------------------------------------
// main fused kernel
// ---------------------------------------------------------------------------
__global__ void __launch_bounds__(THREADS, 2)
fused_kernel(const float* __restrict__ tpts,
             const float* __restrict__ bigpts,
             const float* __restrict__ viewdir,
             const float* __restrict__ b2g,
             const int* __restrict__ tflag,
             float* __restrict__ out) {
    extern __shared__ unsigned char smc[];
    const int tid  = threadIdx.x;
    const int lane = tid & 31;
    const int wid  = tid >> 5;
    const int wy   = wid >> 2;          // layer2: m tile of 32
    const int wx   = wid & 3;           // layer2: n tile of 64
    const int n0   = blockIdx.x * TM;

    const unsigned sb = smem_to_u32(smc);

    // ---- layer2 A ldmatrix bases (validated R6-R13) ----
    unsigned a_rb[2], a_msk[2];
#pragma unroll
    for (int mt = 0; mt < 2; ++mt) {
        int ml = wy * 32 + mt * 16 + (lane & 15);
        a_rb[mt]  = (unsigned)(ml * 512 + (lane >> 4) * 16);
        a_msk[mt] = (unsigned)((ml & 7) << 4);
    }
    // ---- layer3 bases: warp w -> m-tile (w>>1), n-half (w&1) ----
    const int ml3 = (wid >> 1) * 16 + (lane & 15);
    const unsigned a3_rb  = (unsigned)(ml3 * 512 + (lane >> 4) * 16);
    const unsigned a3_msk = (unsigned)((ml3 & 7) << 4);
    const int nh = wid & 1;
    const int r0 = (wid >> 1) * 16 + (lane >> 2);
    const int r1 = r0 + 8;
    const int cbase = nh * 16 + (lane & 3) * 2;

    float sums[2][4];
#pragma unroll
    for (int t = 0; t < 2; ++t)
#pragma unroll
        for (int q = 0; q < 4; ++q) sums[t][q] = 0.f;

    for (int p = 0; p < PPARTS; ++p) {
        const uint4* bbase = g_B2 + (size_t)(p * 4 + wx) * 2048 + lane;

        // prefetch first half-stage's B fragments (hides behind layer1+bar)
        uint4 b0[4], b1[4];
#pragma unroll
        for (int t = 0; t < 4; ++t) b0[t] = __ldg(bbase + t * 32);

        // ---------------- layer 1 (thread = (m, d-chunk of 64)) ----------
        {
            const int m1 = tid & 63;
            const int dc = tid >> 6;
            const int gi = (n0 + m1) * PPARTS + p;
            float x[9];
            x[0] = tpts[gi*3];    x[1] = tpts[gi*3+1];    x[2] = tpts[gi*3+2];
            x[3] = bigpts[gi*3];  x[4] = bigpts[gi*3+1];  x[5] = bigpts[gi*3+2];
            x[6] = viewdir[gi*3]; x[7] = viewdir[gi*3+1]; x[8] = viewdir[gi*3+2];
            const float* w1  = g_W1r + p * 2304;
            const float* b1e = g_b1eff + p * 256;
            const unsigned amask = (unsigned)((m1 & 7) << 4);
            const unsigned mrow  = (unsigned)(m1 * 512 + dc * 128);
#pragma unroll 4
            for (int gq = 0; gq < 16; ++gq) {
                const int d = dc * 64 + gq * 4;
                float4 a = *(const float4*)(b1e + d);
#pragma unroll
                for (int i = 0; i < 9; ++i) {
                    float4 w = *(const float4*)(w1 + i * 256 + d);
                    a.x += x[i]*w.x; a.y += x[i]*w.y;
                    a.z += x[i]*w.z; a.w += x[i]*w.w;
                }
                a.x = fmaxf(a.x, 0.f); a.y = fmaxf(a.y, 0.f);
                a.z = fmaxf(a.z, 0.f); a.w = fmaxf(a.w, 0.f);
                unsigned o0 = (mrow + gq * 8) ^ amask;
                unsigned o1 = (mrow + gq * 8 + 4) ^ amask;
                *(unsigned*)(smc + OFF_AHI + o0) = pack_h2(a.x, a.y);
                *(unsigned*)(smc + OFF_AHI + o1) = pack_h2(a.z, a.w);
            }
        }
        __syncthreads();   // (1) A plane ready CTA-wide

        // ---------------- layer 2: reg-pipelined B, barrier-free ---------
        float acc[2][8][4];
#pragma unroll
        for (int mt = 0; mt < 2; ++mt)
#pragma unroll
            for (int nt = 0; nt < 8; ++nt)
#pragma unroll
                for (int q = 0; q < 4; ++q) acc[mt][nt][q] = 0.f;

#pragma unroll 1
        for (int hs = 0; hs < 16; hs += 2) {
#pragma unroll
            for (int t = 0; t < 4; ++t)
                b1[t] = __ldg(bbase + (hs + 1) * 128 + t * 32);
            {
                const unsigned cc = (unsigned)(hs * 32);
                unsigned ah[2][4];
                LDSM4(ah[0], sb + OFF_AHI + ((a_rb[0] + cc) ^ a_msk[0]));
                LDSM4(ah[1], sb + OFF_AHI + ((a_rb[1] + cc) ^ a_msk[1]));
#pragma unroll
                for (int mt = 0; mt < 2; ++mt)
#pragma unroll
                    for (int t = 0; t < 4; ++t) {
                        MMA16816(acc[mt][2*t],   ah[mt], b0[t].x, b0[t].y);
                        MMA16816(acc[mt][2*t+1], ah[mt], b0[t].z, b0[t].w);
                    }
            }
            if (hs + 2 < 16) {
#pragma unroll
                for (int t = 0; t < 4; ++t)
                    b0[t] = __ldg(bbase + (hs + 2) * 128 + t * 32);
            }
            {
                const unsigned cc = (unsigned)(hs * 32 + 32);
                unsigned ah[2][4];
                LDSM4(ah[0], sb + OFF_AHI + ((a_rb[0] + cc) ^ a_msk[0]));
                LDSM4(ah[1], sb + OFF_AHI + ((a_rb[1] + cc) ^ a_msk[1]));
#pragma unroll
                for (int mt = 0; mt < 2; ++mt)
#pragma unroll
                    for (int t = 0; t < 4; ++t) {
                        MMA16816(acc[mt][2*t],   ah[mt], b1[t].x, b1[t].y);
                        MMA16816(acc[mt][2*t+1], ah[mt], b1[t].z, b1[t].w);
                    }
            }
        }
        // no barrier: epilogue writes OFF_H2, disjoint from OFF_AHI reads

        // ---------------- epilogue: acc -> h2 fp16 plane (hi only) -------
#pragma unroll
        for (int mt = 0; mt < 2; ++mt) {
            const int row0 = wy * 32 + mt * 16 + (lane >> 2);
#pragma unroll
            for (int nt = 0; nt < 8; ++nt) {
                const int e = wx * 64 + nt * 8 + (lane & 3) * 2;
                float2 bv = *(const float2*)(b2g + p * 256 + e);
                float v0 = fmaxf(acc[mt][nt][0] + bv.x, 0.f);
                float v1 = fmaxf(acc[mt][nt][1] + bv.y, 0.f);
                float v2 = fmaxf(acc[mt][nt][2] + bv.x, 0.f);
                float v3 = fmaxf(acc[mt][nt][3] + bv.y, 0.f);
                unsigned o0 = (unsigned)(row0 * 512 + e * 2) ^
                              (unsigned)((row0 & 7) << 4);
                unsigned o1 = (unsigned)((row0 + 8) * 512 + e * 2) ^
                              (unsigned)(((row0 + 8) & 7) << 4);
                *(unsigned*)(smc + OFF_H2 + o0) = pack_h2(v0, v1);
                *(unsigned*)(smc + OFF_H2 + o1) = pack_h2(v2, v3);
            }
        }
        __syncthreads();   // (2) h2 plane visible CTA-wide
                           //     (also: all layer2 A reads done)

        // ---------------- layer 3: single chain, pipelined B -------------
        float acc3[2][4];
#pragma unroll
        for (int t = 0; t < 2; ++t)
#pragma unroll
            for (int q = 0; q < 4; ++q) acc3[t][q] = 0.f;
        {
            const uint4* bhi = g_B3 + (size_t)(p * 2 + nh) * 512 + lane;
            uint4 bh = __ldg(bhi);
#pragma unroll 1
            for (int ks = 0; ks < 16; ++ks) {
                uint4 bhc = bh;
                if (ks + 1 < 16) bh = __ldg(bhi + (ks + 1) * 32);
                const unsigned cc = (unsigned)(ks * 32);
                unsigned ah[4];
                LDSM4(ah, sb + OFF_H2 + ((a3_rb + cc) ^ a3_msk));
                MMA16816(acc3[0], ah, bhc.x, bhc.y);
                MMA16816(acc3[1], ah, bhc.z, bhc.w);
            }
        }

        // ---------------- extraction: mask, sigmoid, accumulate ----------
        {
            const float fl0 = (tflag[(n0 + r0) * PPARTS + p] != 0) ? 1.f : 0.f;
            const float fl1 = (tflag[(n0 + r1) * PPARTS + p] != 0) ? 1.f : 0.f;
#pragma unroll
            for (int t = 0; t < 2; ++t) {
                const int c = cbase + t * 8;
                const float b3a = g_b3[p * 32 + c];
                const float b3b = g_b3[p * 32 + c + 1];
                float v0 = acc3[t][0] + b3a, v1 = acc3[t][1] + b3b;
                float v2 = acc3[t][2] + b3a, v3 = acc3[t][3] + b3b;
                if (c == 20) {
                    v0 = (1.f / (1.f + __expf(-v0))) * fl0;
                    v2 = (1.f / (1.f + __expf(-v2))) * fl1;
                    out[(size_t)(n0 + r0) * OUTC + 21 + p] = v0;   // tocc
                    out[(size_t)(n0 + r1) * OUTC + 21 + p] = v2;
                } else {
                    v0 *= fl0; v2 *= fl1;
                }
                v1 *= fl0; v3 *= fl1;
                sums[t][0] += v0; sums[t][1] += v1;
                sums[t][2] += v2; sums[t][3] += v3;
            }
        }
        __syncthreads();   // (3) layer3 h2 reads done; A plane free for next p
    }

    // ---------------- final masked means ----------------
    const float inv6 = 1.f / 6.f;
#pragma unroll
    for (int t = 0; t < 2; ++t) {
        const int c = cbase + t * 8;
        if (c < 21) {
            out[(size_t)(n0 + r0) * OUTC + c] = sums[t][0] * inv6;
            out[(size_t)(n0 + r1) * OUTC + c] = sums[t][2] * inv6;
        }
        if (c + 1 < 21) {
            out[(size_t)(n0 + r0) * OUTC + c + 1] = sums[t][1] * inv6;
            out[(size_t)(n0 + r1) * OUTC + c + 1] = sums[t][3] * inv6;
        }
    }
}

// ---------------------------------------------------------------------------
// launch
// ---------------------------------------------------------------------------
extern "C" void kernel_launch(void* const* d_in, const int* in_sizes, int n_in,
                              void* d_out, int out_size) {
    const float* tpts    = (const float*)d_in[0];
    const float* bigpts  = (const float*)d_in[1];
    const float* viewdir = (const float*)d_in[2];
    // d_in[3]=dists, d_in[4]=part_dist unused
    const float* frame   = (const float*)d_in[5];
    const float* W1      = (const float*)d_in[6];
    const float* b1      = (const float*)d_in[7];
    const float* W2      = (const float*)d_in[8];
    const float* b2      = (const float*)d_in[9];
    const float* W3      = (const float*)d_in[10];
    const float* b3      = (const float*)d_in[11];
    const float* Wocc    = (const float*)d_in[12];
    const float* bocc    = (const float*)d_in[13];
    const int*   tflag   = (const int*)d_in[14];
    float* out = (float*)d_out;

    prep_small<<<PPARTS, 256>>>(W1, b1, b3, bocc, frame);
    prep_B2<<<dim3(PPARTS, 8, 4), 256>>>(W2);
    prep_B3<<<dim3(PPARTS, 16), 64>>>(W3, Wocc);

    cudaFuncSetAttribute(fused_kernel,
                         cudaFuncAttributeMaxDynamicSharedMemorySize,
                         SMEM_BYTES);
    fused_kernel<<<NCTAS, THREADS, SMEM_BYTES>>>(tpts, bigpts, viewdir,
                                                 b2, tflag, out);
}